// round 14
// baseline (speedup 1.0000x reference)
#include <cuda_runtime.h>

// Problem constants
constexpr int Nn = 4096;   // nodes
constexpr int Dd = 256;    // model dim
constexpr int Ee = 65536;  // edges
constexpr int DCAP = 64;   // per-row bucket capacity

// Out GEMM (unchanged)
constexpr int BK2 = 32;
constexpr int KP2 = 36;
constexpr int SMEM_A2 = 64 * KP2;
constexpr int SMEM_W2 = 128 * KP2;
constexpr int SMEM2_BYTES = 2 * (SMEM_A2 + SMEM_W2) * 4;  // 55296

// QKV GEMM: fragment-linear operands, BM=64/BN=128, 4-stage cp.async ring
constexpr int QKV_STAGES = 4;
constexpr int STAGE_FLOATS = 3072;   // 1024 A (64x16) + 2048 W (128x16)
constexpr int QKV_SMEM_BYTES = QKV_STAGES * STAGE_FLOATS * 4;  // 49152

// ---------------------------------------------------------------------------
// Scratch
// ---------------------------------------------------------------------------
__device__ float    g_Q[Nn * Dd];
__device__ float    g_K[Nn * Dd];
__device__ float    g_V[Nn * Dd];
__device__ float    g_attn[Nn * Dd];
__device__ float    g_vsum[Dd];
__device__ int      g_cnt[Nn];
__device__ int      g_adj[Nn * DCAP];
// permuted (fragment-linear) tf32-rounded operands for the QKV GEMM
__device__ float    g_xp[Nn * Dd];
__device__ float    g_Wqp[Dd * Dd];
__device__ float    g_Wkp[Dd * Dd];
__device__ float    g_Wvp[Dd * Dd];
// standard-layout rounded Wo for the out-GEMM
__device__ float    g_Wor[Dd * Dd];

// ---------------------------------------------------------------------------
__device__ __forceinline__ float tf32_rna(float f) {
    unsigned u;
    asm("cvt.rna.tf32.f32 %0, %1;" : "=r"(u) : "f"(f));
    return __uint_as_float(u);
}

__global__ void zero_small_kernel() {
    int idx = blockIdx.x * blockDim.x + threadIdx.x;
    if (idx < Nn) g_cnt[idx] = 0;
    if (idx < Dd) g_vsum[idx] = 0.0f;
}

__global__ void bucket_kernel(const int* __restrict__ ei) {
    int e = blockIdx.x * blockDim.x + threadIdx.x;
    if (e >= Ee) return;
    int row = ei[e] & (Nn - 1);
    int col = ei[Ee + e] & (Nn - 1);
    int p = atomicAdd(&g_cnt[row], 1);
    if (p < DCAP) g_adj[row * DCAP + p] = col;
}

// ---------------------------------------------------------------------------
// Permute + tf32-round pass (fragment-linear layouts; unchanged).
// ---------------------------------------------------------------------------
__global__ void permute_kernel(const float* __restrict__ x,
                               const float* __restrict__ Wq,
                               const float* __restrict__ Wk,
                               const float* __restrict__ Wv,
                               const float* __restrict__ Wo) {
    int idx = blockIdx.x * blockDim.x + threadIdx.x;
    int stride = gridDim.x * blockDim.x;

    for (int cidx = idx; cidx < Nn * Dd / 4; cidx += stride) {
        int lane   = cidx & 31;
        int kk     = (cidx >> 5) & 1;
        int mblk   = (cidx >> 6) & 7;
        int kblk   = (cidx >> 9) & 15;
        int mpanel = cidx >> 13;
        int m = mpanel * 128 + mblk * 16 + (lane >> 2);
        int k = kblk * 16 + kk * 8 + (lane & 3);
        float4 v;
        v.x = tf32_rna(x[(size_t)m * Dd + k]);
        v.y = tf32_rna(x[(size_t)(m + 8) * Dd + k]);
        v.z = tf32_rna(x[(size_t)m * Dd + k + 4]);
        v.w = tf32_rna(x[(size_t)(m + 8) * Dd + k + 4]);
        ((float4*)g_xp)[cidx] = v;
    }

    for (int cidx = idx; cidx < Dd * Dd / 4; cidx += stride) {
        int lane   = cidx & 31;
        int nblk   = (cidx >> 5) & 15;
        int kblk   = (cidx >> 9) & 15;
        int npanel = cidx >> 13;
        int n  = npanel * 128 + nblk * 8 + (lane >> 2);
        int kb = kblk * 16 + (lane & 3);
        size_t s = (size_t)n * Dd + kb;
        float4 vq, vk, vv;
        vq.x = tf32_rna(Wq[s]);      vq.y = tf32_rna(Wq[s + 4]);
        vq.z = tf32_rna(Wq[s + 8]);  vq.w = tf32_rna(Wq[s + 12]);
        vk.x = tf32_rna(Wk[s]);      vk.y = tf32_rna(Wk[s + 4]);
        vk.z = tf32_rna(Wk[s + 8]);  vk.w = tf32_rna(Wk[s + 12]);
        vv.x = tf32_rna(Wv[s]);      vv.y = tf32_rna(Wv[s + 4]);
        vv.z = tf32_rna(Wv[s + 8]);  vv.w = tf32_rna(Wv[s + 12]);
        ((float4*)g_Wqp)[cidx] = vq;
        ((float4*)g_Wkp)[cidx] = vk;
        ((float4*)g_Wvp)[cidx] = vv;
    }

    for (int i = idx; i < Dd * Dd; i += stride) g_Wor[i] = tf32_rna(Wo[i]);
}

// ---------------------------------------------------------------------------
// Shared GEMM helpers
// ---------------------------------------------------------------------------
__device__ __forceinline__ unsigned smem_u32(const void* p) {
    return (unsigned)__cvta_generic_to_shared(p);
}
__device__ __forceinline__ void cp_async16(unsigned dst, const void* src) {
    asm volatile("cp.async.cg.shared.global [%0], [%1], 16;" :: "r"(dst), "l"(src));
}
__device__ __forceinline__ void cp_commit() {
    asm volatile("cp.async.commit_group;" ::: "memory");
}
template <int N> __device__ __forceinline__ void cp_wait() {
    asm volatile("cp.async.wait_group %0;" :: "n"(N) : "memory");
}
__device__ __forceinline__ void mma_tf32(float* d, float a0, float a1, float a2, float a3,
                                         float b0, float b1) {
    asm volatile(
        "mma.sync.aligned.m16n8k8.row.col.f32.tf32.tf32.f32 "
        "{%0,%1,%2,%3}, {%4,%5,%6,%7}, {%8,%9}, {%0,%1,%2,%3};\n"
        : "+f"(d[0]), "+f"(d[1]), "+f"(d[2]), "+f"(d[3])
        : "r"(__float_as_uint(a0)), "r"(__float_as_uint(a1)),
          "r"(__float_as_uint(a2)), "r"(__float_as_uint(a3)),
          "r"(__float_as_uint(b0)), "r"(__float_as_uint(b1)));
}

// ---------------------------------------------------------------------------
// QKV GEMM, fragment-linear, BM=64 / BN=128, 256 threads = 8 warps
// (2m x 4n), warp tile 32x32. Same 384-CTA single-wave grid as R13, but
// ~20.7 resident warps/SM (was 10.4): doubles SMSP latency hiding at
// identical instruction totals. Per k-tile per warp: 8 LDS.128 + 16 mma.
// ---------------------------------------------------------------------------
__global__ __launch_bounds__(256, 3) void gemm_qkv_kernel() {
    extern __shared__ __align__(16) float smem[];
    const float* Wp = (blockIdx.z == 0) ? g_Wqp : (blockIdx.z == 1) ? g_Wkp : g_Wvp;
    float* C = (blockIdx.z == 0) ? g_Q : (blockIdx.z == 1) ? g_K : g_V;

    const int tid  = threadIdx.x;
    const int lane = tid & 31;
    const int wid  = tid >> 5;          // 0..7
    const int wm   = wid & 1;           // m half (32 rows)
    const int wn   = wid >> 1;          // n group (32 cols)
    const unsigned sbase = smem_u32(smem);

    const int mp128 = blockIdx.y >> 1;  // 128-row panel in g_xp
    const int half  = blockIdx.y & 1;   // which 64-row half

    float d[2][4][4];
#pragma unroll
    for (int i = 0; i < 2; i++)
#pragma unroll
        for (int j = 0; j < 4; j++)
#pragma unroll
            for (int q = 0; q < 4; q++) d[i][j][q] = 0.0f;

    auto stage = [&](int s, int t) {
        unsigned dstA = sbase + (unsigned)(s * STAGE_FLOATS) * 4u;
        const float* srcA = g_xp + ((size_t)mp128 * 16 + t) * 2048 + half * 1024;
        cp_async16(dstA + tid * 16, srcA + (size_t)tid * 4);
        unsigned dstW = dstA + 1024 * 4;
        const float* srcW = Wp + ((size_t)blockIdx.x * 16 + t) * 2048;
        cp_async16(dstW + tid * 16, srcW + (size_t)tid * 4);
        cp_async16(dstW + (tid + 256) * 16, srcW + (size_t)(tid + 256) * 4);
        cp_commit();
    };

    stage(0, 0); stage(1, 1); stage(2, 2);

    constexpr int NT = Dd / 16;  // 16 k-tiles
    for (int t = 0; t < NT; t++) {
        if (t + 3 < NT) { stage((t + 3) & 3, t + 3); cp_wait<3>(); }
        else            { cp_wait<0>(); }
        __syncthreads();

        const float4* As4 = (const float4*)(smem + (t & 3) * STAGE_FLOATS);
        const float4* Ws4 = (const float4*)(smem + (t & 3) * STAGE_FLOATS + 1024);

        float4 bv[4];
#pragma unroll
        for (int j = 0; j < 4; j++)
            bv[j] = Ws4[(wn * 4 + j) * 32 + lane];

#pragma unroll
        for (int kk = 0; kk < 2; kk++) {
            float4 av[2];
#pragma unroll
            for (int i = 0; i < 2; i++)
                av[i] = As4[((wm * 2 + i) * 2 + kk) * 32 + lane];
#pragma unroll
            for (int i = 0; i < 2; i++)
#pragma unroll
                for (int j = 0; j < 4; j++)
                    mma_tf32(d[i][j], av[i].x, av[i].y, av[i].z, av[i].w,
                             kk ? bv[j].z : bv[j].x, kk ? bv[j].w : bv[j].y);
        }
        __syncthreads();
    }

    // Epilogue
    const int r = lane >> 2, c = lane & 3;
    const int m0 = blockIdx.y * 64 + wm * 32;
    const int n0 = blockIdx.x * 128 + wn * 32;
#pragma unroll
    for (int i = 0; i < 2; i++) {
#pragma unroll
        for (int j = 0; j < 4; j++) {
            int m = m0 + 16 * i + r;
            int n = n0 + 8 * j + 2 * c;
            *(float2*)&C[(size_t)m * Dd + n] = make_float2(d[i][j][0], d[i][j][1]);
            *(float2*)&C[(size_t)(m + 8) * Dd + n] = make_float2(d[i][j][2], d[i][j][3]);
        }
    }
}

// ---------------------------------------------------------------------------
// Out-proj GEMM (unchanged): BM=64, BN=128, BK=32, 128 CTAs.
// ---------------------------------------------------------------------------
__global__ __launch_bounds__(256, 3) void gemm_out_kernel(const float* __restrict__ bo,
                                                          float* __restrict__ out) {
    extern __shared__ __align__(16) float smem[];
    float* As0 = smem;
    float* Ws0 = smem + 2 * SMEM_A2;

    const float* A = g_attn;
    const float* W = g_Wor;

    const int tid  = threadIdx.x;
    const int lane = tid & 31;
    const int wid  = tid >> 5;
    const int wm0  = (wid & 1) * 32;
    const int wn0  = (wid >> 1) * 32;
    const int m0   = blockIdx.y * 64;
    const int n0   = blockIdx.x * 128;

    const int r = lane >> 2;
    const int c = lane & 3;

    const int rA = tid >> 2;
    const int kA = (tid & 3) * 8;
    const int rW = tid >> 1;
    const int kW = (tid & 1) * 16;

    float d[2][4][4];
#pragma unroll
    for (int i = 0; i < 2; i++)
#pragma unroll
        for (int j = 0; j < 4; j++)
#pragma unroll
            for (int q = 0; q < 4; q++) d[i][j][q] = 0.0f;

    auto do_stage = [&](int s, int t) {
        float* As = As0 + s * SMEM_A2;
        float* Ws = Ws0 + s * SMEM_W2;
        unsigned a_dst = smem_u32(&As[rA * KP2 + kA]);
        const float* a_src = &A[(size_t)(m0 + rA) * Dd + t * BK2 + kA];
        cp_async16(a_dst,      a_src);
        cp_async16(a_dst + 16, a_src + 4);
        unsigned w_dst = smem_u32(&Ws[rW * KP2 + kW]);
        const float* w_src = &W[(size_t)(n0 + rW) * Dd + t * BK2 + kW];
        cp_async16(w_dst,      w_src);
        cp_async16(w_dst + 16, w_src + 4);
        cp_async16(w_dst + 32, w_src + 8);
        cp_async16(w_dst + 48, w_src + 12);
        cp_commit();
    };

    do_stage(0, 0);

    constexpr int NT = Dd / BK2;
    for (int t = 0; t < NT; t++) {
        if (t + 1 < NT) { do_stage((t + 1) & 1, t + 1); cp_wait<1>(); }
        else            { cp_wait<0>(); }
        __syncthreads();
        const int s = t & 1;
        const float* As = As0 + s * SMEM_A2;
        const float* Ws = Ws0 + s * SMEM_W2;

#pragma unroll
        for (int kk = 0; kk < BK2; kk += 8) {
            float a[2][4], b[4][2];
#pragma unroll
            for (int i = 0; i < 2; i++) {
                const float* p = &As[(wm0 + 16 * i + r) * KP2 + kk + c];
                a[i][0] = p[0];
                a[i][1] = p[8 * KP2];
                a[i][2] = p[4];
                a[i][3] = p[8 * KP2 + 4];
            }
#pragma unroll
            for (int j = 0; j < 4; j++) {
                const float* p = &Ws[(wn0 + 8 * j + r) * KP2 + kk + c];
                b[j][0] = p[0];
                b[j][1] = p[4];
            }
#pragma unroll
            for (int i = 0; i < 2; i++)
#pragma unroll
                for (int j = 0; j < 4; j++)
                    mma_tf32(d[i][j], a[i][0], a[i][1], a[i][2], a[i][3],
                             b[j][0], b[j][1]);
        }
        __syncthreads();
    }

#pragma unroll
    for (int i = 0; i < 2; i++) {
#pragma unroll
        for (int j = 0; j < 4; j++) {
            int m = m0 + wm0 + 16 * i + r;
            int n = n0 + wn0 + 8 * j + 2 * c;
            float bx = bo[n], by = bo[n + 1];
            *(float2*)&out[(size_t)m * Dd + n] =
                make_float2(d[i][j][0] + bx, d[i][j][1] + by);
            *(float2*)&out[(size_t)(m + 8) * Dd + n] =
                make_float2(d[i][j][2] + bx, d[i][j][3] + by);
        }
    }
}

// ---------------------------------------------------------------------------
// Column sums of V
// ---------------------------------------------------------------------------
__global__ void vsum_kernel() {
    int c = threadIdx.x;
    int r0 = blockIdx.x * 16;
    float s = 0.0f;
#pragma unroll
    for (int r = 0; r < 16; r++) s += g_V[(size_t)(r0 + r) * Dd + c];
    atomicAdd(&g_vsum[c], s);
}

// ---------------------------------------------------------------------------
// Row kernel: one WARP per row (unchanged winner).
// ---------------------------------------------------------------------------
__device__ __forceinline__ void edge_accum(int col, int lane, const float* q,
                                           float* acc, float& dn) {
    const float* kp = g_K + (size_t)col * Dd + lane * 8;
    const float* vp = g_V + (size_t)col * Dd + lane * 8;
    float4 k1 = *(const float4*)kp;
    float4 k2 = *(const float4*)(kp + 4);
    float4 v1 = *(const float4*)vp;
    float4 v2 = *(const float4*)(vp + 4);
    float s = q[0] * k1.x + q[1] * k1.y + q[2] * k1.z + q[3] * k1.w
            + q[4] * k2.x + q[5] * k2.y + q[6] * k2.z + q[7] * k2.w;
    s += __shfl_xor_sync(0xffffffffu, s, 1);
    s += __shfl_xor_sync(0xffffffffu, s, 2);
    const float inv_scale = 0.17677669529663687f;
    float w = __expf(s * inv_scale) - 1.0f;
    acc[0] += w * v1.x; acc[1] += w * v1.y; acc[2] += w * v1.z; acc[3] += w * v1.w;
    acc[4] += w * v2.x; acc[5] += w * v2.y; acc[6] += w * v2.z; acc[7] += w * v2.w;
    dn += w;
}

__global__ __launch_bounds__(256) void row_kernel() {
    const int lane = threadIdx.x & 31;
    const int row  = blockIdx.x * 8 + (threadIdx.x >> 5);

    const int deg = min(g_cnt[row], DCAP);
    const int* adj = g_adj + row * DCAP;

    int col0 = (lane < deg)      ? adj[lane]      : (-1 - lane);
    int col1 = (32 + lane < deg) ? adj[32 + lane] : (-1 - lane);

    unsigned m0 = __match_any_sync(0xffffffffu, col0);
    bool keep0 = (lane < deg) && (lane == __ffs(m0) - 1);
    unsigned bm0 = __ballot_sync(0xffffffffu, keep0);

    unsigned bm1 = 0u;
    if (deg > 32) {
        unsigned m1 = __match_any_sync(0xffffffffu, col1);
        bool keep1 = (32 + lane < deg) && (lane == __ffs(m1) - 1);
        for (int j = 0; j < 32; j++) {
            int cj = __shfl_sync(0xffffffffu, col0, j);
            if (j < deg && cj == col1) keep1 = false;
        }
        bm1 = __ballot_sync(0xffffffffu, keep1);
    }

    float q[8];
    {
        const float* qp = g_Q + (size_t)row * Dd + lane * 8;
        float4 a = *(const float4*)qp;
        float4 b = *(const float4*)(qp + 4);
        q[0] = a.x; q[1] = a.y; q[2] = a.z; q[3] = a.w;
        q[4] = b.x; q[5] = b.y; q[6] = b.z; q[7] = b.w;
    }

    float acc[8] = {0, 0, 0, 0, 0, 0, 0, 0};
    float dn = 0.0f;

#pragma unroll 1
    for (int ch = 0; ch < 2; ch++) {
        unsigned bm = (ch == 0) ? bm0 : bm1;
        int cols = (ch == 0) ? col0 : col1;
        while (bm) {
            int b0 = __ffs(bm) - 1; bm &= bm - 1;
            int cA = __shfl_sync(0xffffffffu, cols, b0);
            if (bm) {
                int b1 = __ffs(bm) - 1; bm &= bm - 1;
                int cB = __shfl_sync(0xffffffffu, cols, b1);
                const float* kA = g_K + (size_t)cA * Dd + lane * 8;
                const float* vA = g_V + (size_t)cA * Dd + lane * 8;
                const float* kB = g_K + (size_t)cB * Dd + lane * 8;
                const float* vB = g_V + (size_t)cB * Dd + lane * 8;
                float4 kA1 = *(const float4*)kA, kA2 = *(const float4*)(kA + 4);
                float4 vA1 = *(const float4*)vA, vA2 = *(const float4*)(vA + 4);
                float4 kB1 = *(const float4*)kB, kB2 = *(const float4*)(kB + 4);
                float4 vB1 = *(const float4*)vB, vB2 = *(const float4*)(vB + 4);

                float sA = q[0]*kA1.x + q[1]*kA1.y + q[2]*kA1.z + q[3]*kA1.w
                         + q[4]*kA2.x + q[5]*kA2.y + q[6]*kA2.z + q[7]*kA2.w;
                float sB = q[0]*kB1.x + q[1]*kB1.y + q[2]*kB1.z + q[3]*kB1.w
                         + q[4]*kB2.x + q[5]*kB2.y + q[6]*kB2.z + q[7]*kB2.w;
                sA += __shfl_xor_sync(0xffffffffu, sA, 1);
                sB += __shfl_xor_sync(0xffffffffu, sB, 1);
                sA += __shfl_xor_sync(0xffffffffu, sA, 2);
                sB += __shfl_xor_sync(0xffffffffu, sB, 2);
                const float inv_scale = 0.17677669529663687f;
                float wA = __expf(sA * inv_scale) - 1.0f;
                float wB = __expf(sB * inv_scale) - 1.0f;
                acc[0] += wA*vA1.x + wB*vB1.x; acc[1] += wA*vA1.y + wB*vB1.y;
                acc[2] += wA*vA1.z + wB*vB1.z; acc[3] += wA*vA1.w + wB*vB1.w;
                acc[4] += wA*vA2.x + wB*vB2.x; acc[5] += wA*vA2.y + wB*vB2.y;
                acc[6] += wA*vA2.z + wB*vB2.z; acc[7] += wA*vA2.w + wB*vB2.w;
                dn += wA + wB;
            } else {
                edge_accum(cA, lane, q, acc, dn);
            }
        }
    }

    float* op = g_attn + (size_t)row * Dd + lane * 8;
    const float* vs = g_vsum + lane * 8;
    float inv_d = 1.0f / ((float)Nn + dn);
    float4 o1, o2;
    o1.x = tf32_rna((vs[0] + acc[0]) * inv_d);
    o1.y = tf32_rna((vs[1] + acc[1]) * inv_d);
    o1.z = tf32_rna((vs[2] + acc[2]) * inv_d);
    o1.w = tf32_rna((vs[3] + acc[3]) * inv_d);
    o2.x = tf32_rna((vs[4] + acc[4]) * inv_d);
    o2.y = tf32_rna((vs[5] + acc[5]) * inv_d);
    o2.z = tf32_rna((vs[6] + acc[6]) * inv_d);
    o2.w = tf32_rna((vs[7] + acc[7]) * inv_d);
    *(float4*)op = o1;
    *(float4*)(op + 4) = o2;
}

// ---------------------------------------------------------------------------
extern "C" void kernel_launch(void* const* d_in, const int* in_sizes, int n_in,
                              void* d_out, int out_size) {
    const float* x  = (const float*)d_in[0];
    const int*   ei = (const int*)d_in[1];     // int32 (JAX x64 disabled)
    const float* Wq = (const float*)d_in[2];
    const float* Wk = (const float*)d_in[3];
    const float* Wv = (const float*)d_in[4];
    const float* Wo = (const float*)d_in[5];
    const float* bo = (const float*)d_in[6];
    float*       out = (float*)d_out;

    cudaFuncSetAttribute(gemm_qkv_kernel,
                         cudaFuncAttributeMaxDynamicSharedMemorySize, QKV_SMEM_BYTES);
    cudaFuncSetAttribute(gemm_out_kernel,
                         cudaFuncAttributeMaxDynamicSharedMemorySize, SMEM2_BYTES);

    zero_small_kernel<<<17, 256>>>();
    bucket_kernel<<<Ee / 256, 256>>>(ei);
    permute_kernel<<<512, 256>>>(x, Wq, Wk, Wv, Wo);
    gemm_qkv_kernel<<<dim3(2, 64, 3), 256, QKV_SMEM_BYTES>>>();
    vsum_kernel<<<Nn / 16, 256>>>();
    row_kernel<<<Nn / 8, 256>>>();
    gemm_out_kernel<<<dim3(Dd / 128, Nn / 64, 1), 256, SMEM2_BYTES>>>(bo, out);
}

// round 15
// speedup vs baseline: 1.1659x; 1.1659x over previous
#include <cuda_runtime.h>

// Problem constants
constexpr int Nn = 4096;   // nodes
constexpr int Dd = 256;    // model dim
constexpr int Ee = 65536;  // edges
constexpr int DCAP = 64;   // per-row bucket capacity

// Fragment-linear GEMM config (R13 winner): BM=64/BN=128, 128 thr, 4 warps
constexpr int QKV_STAGES = 4;
constexpr int STAGE_FLOATS = 3072;   // 1024 A (64x16) + 2048 W (128x16)
constexpr int QKV_SMEM_BYTES = QKV_STAGES * STAGE_FLOATS * 4;  // 49152

// ---------------------------------------------------------------------------
// Scratch
// ---------------------------------------------------------------------------
__device__ float    g_Q[Nn * Dd];
__device__ float    g_K[Nn * Dd];
__device__ float    g_V[Nn * Dd];
__device__ float    g_attnp[Nn * Dd];   // attn in A-fragment-linear layout
__device__ float    g_vsum[Dd];
__device__ int      g_cnt[Nn];
__device__ int      g_adj[Nn * DCAP];
// permuted (fragment-linear) tf32-rounded operands
__device__ float    g_xp[Nn * Dd];
__device__ float    g_Wqp[Dd * Dd];
__device__ float    g_Wkp[Dd * Dd];
__device__ float    g_Wvp[Dd * Dd];
__device__ float    g_Wop[Dd * Dd];

// ---------------------------------------------------------------------------
__device__ __forceinline__ float tf32_rna(float f) {
    unsigned u;
    asm("cvt.rna.tf32.f32 %0, %1;" : "=r"(u) : "f"(f));
    return __uint_as_float(u);
}

__global__ void zero_small_kernel() {
    int idx = blockIdx.x * blockDim.x + threadIdx.x;
    if (idx < Nn) g_cnt[idx] = 0;
    if (idx < Dd) g_vsum[idx] = 0.0f;
}

__global__ void bucket_kernel(const int* __restrict__ ei) {
    int e = blockIdx.x * blockDim.x + threadIdx.x;
    if (e >= Ee) return;
    int row = ei[e] & (Nn - 1);
    int col = ei[Ee + e] & (Nn - 1);
    int p = atomicAdd(&g_cnt[row], 1);
    if (p < DCAP) g_adj[row * DCAP + p] = col;
}

// ---------------------------------------------------------------------------
// Permute + tf32-round pass. A-layout (x) and B-layout (Wq,Wk,Wv,Wo).
// ---------------------------------------------------------------------------
__global__ void permute_kernel(const float* __restrict__ x,
                               const float* __restrict__ Wq,
                               const float* __restrict__ Wk,
                               const float* __restrict__ Wv,
                               const float* __restrict__ Wo) {
    int idx = blockIdx.x * blockDim.x + threadIdx.x;
    int stride = gridDim.x * blockDim.x;

    for (int cidx = idx; cidx < Nn * Dd / 4; cidx += stride) {
        int lane   = cidx & 31;
        int kk     = (cidx >> 5) & 1;
        int mblk   = (cidx >> 6) & 7;
        int kblk   = (cidx >> 9) & 15;
        int mpanel = cidx >> 13;
        int m = mpanel * 128 + mblk * 16 + (lane >> 2);
        int k = kblk * 16 + kk * 8 + (lane & 3);
        float4 v;
        v.x = tf32_rna(x[(size_t)m * Dd + k]);
        v.y = tf32_rna(x[(size_t)(m + 8) * Dd + k]);
        v.z = tf32_rna(x[(size_t)m * Dd + k + 4]);
        v.w = tf32_rna(x[(size_t)(m + 8) * Dd + k + 4]);
        ((float4*)g_xp)[cidx] = v;
    }

    for (int cidx = idx; cidx < Dd * Dd / 4; cidx += stride) {
        int lane   = cidx & 31;
        int nblk   = (cidx >> 5) & 15;
        int kblk   = (cidx >> 9) & 15;
        int npanel = cidx >> 13;
        int n  = npanel * 128 + nblk * 8 + (lane >> 2);
        int kb = kblk * 16 + (lane & 3);
        size_t s = (size_t)n * Dd + kb;
        float4 vq, vk, vv, vo;
        vq.x = tf32_rna(Wq[s]);      vq.y = tf32_rna(Wq[s + 4]);
        vq.z = tf32_rna(Wq[s + 8]);  vq.w = tf32_rna(Wq[s + 12]);
        vk.x = tf32_rna(Wk[s]);      vk.y = tf32_rna(Wk[s + 4]);
        vk.z = tf32_rna(Wk[s + 8]);  vk.w = tf32_rna(Wk[s + 12]);
        vv.x = tf32_rna(Wv[s]);      vv.y = tf32_rna(Wv[s + 4]);
        vv.z = tf32_rna(Wv[s + 8]);  vv.w = tf32_rna(Wv[s + 12]);
        vo.x = tf32_rna(Wo[s]);      vo.y = tf32_rna(Wo[s + 4]);
        vo.z = tf32_rna(Wo[s + 8]);  vo.w = tf32_rna(Wo[s + 12]);
        ((float4*)g_Wqp)[cidx] = vq;
        ((float4*)g_Wkp)[cidx] = vk;
        ((float4*)g_Wvp)[cidx] = vv;
        ((float4*)g_Wop)[cidx] = vo;
    }
}

// ---------------------------------------------------------------------------
// Shared GEMM helpers
// ---------------------------------------------------------------------------
__device__ __forceinline__ unsigned smem_u32(const void* p) {
    return (unsigned)__cvta_generic_to_shared(p);
}
__device__ __forceinline__ void cp_async16(unsigned dst, const void* src) {
    asm volatile("cp.async.cg.shared.global [%0], [%1], 16;" :: "r"(dst), "l"(src));
}
__device__ __forceinline__ void cp_commit() {
    asm volatile("cp.async.commit_group;" ::: "memory");
}
template <int N> __device__ __forceinline__ void cp_wait() {
    asm volatile("cp.async.wait_group %0;" :: "n"(N) : "memory");
}
__device__ __forceinline__ void mma_tf32(float* d, float a0, float a1, float a2, float a3,
                                         float b0, float b1) {
    asm volatile(
        "mma.sync.aligned.m16n8k8.row.col.f32.tf32.tf32.f32 "
        "{%0,%1,%2,%3}, {%4,%5,%6,%7}, {%8,%9}, {%0,%1,%2,%3};\n"
        : "+f"(d[0]), "+f"(d[1]), "+f"(d[2]), "+f"(d[3])
        : "r"(__float_as_uint(a0)), "r"(__float_as_uint(a1)),
          "r"(__float_as_uint(a2)), "r"(__float_as_uint(a3)),
          "r"(__float_as_uint(b0)), "r"(__float_as_uint(b1)));
}

// ---------------------------------------------------------------------------
// Fragment-linear GEMM body (R13 winner): BM=64/BN=128, 128 thr = 4 warps,
// warp-tile 64x32. Per k-tile per warp: 12 LDS.128 + 32 mma.
// ---------------------------------------------------------------------------
template <bool FUSE_VSUM, bool BIAS>
__device__ __forceinline__ void gemm_frag_body(const float* __restrict__ Ap,
                                               const float* __restrict__ Wp,
                                               const float* __restrict__ bias,
                                               float* __restrict__ C,
                                               int by, int bx) {
    extern __shared__ __align__(16) float smem[];
    const int tid  = threadIdx.x;
    const int lane = tid & 31;
    const int wid  = tid >> 5;          // 0..3 -> n-block group
    const unsigned sbase = smem_u32(smem);

    const int mp128 = by >> 1;
    const int half  = by & 1;

    float d[4][4][4];
#pragma unroll
    for (int i = 0; i < 4; i++)
#pragma unroll
        for (int j = 0; j < 4; j++)
#pragma unroll
            for (int q = 0; q < 4; q++) d[i][j][q] = 0.0f;

    auto stage = [&](int s, int t) {
        unsigned dstA = sbase + (unsigned)(s * STAGE_FLOATS) * 4u;
        const float* srcA = Ap + ((size_t)mp128 * 16 + t) * 2048 + half * 1024;
        cp_async16(dstA + tid * 16, srcA + (size_t)tid * 4);
        cp_async16(dstA + (tid + 128) * 16, srcA + (size_t)(tid + 128) * 4);
        unsigned dstW = dstA + 1024 * 4;
        const float* srcW = Wp + ((size_t)bx * 16 + t) * 2048;
        cp_async16(dstW + tid * 16, srcW + (size_t)tid * 4);
        cp_async16(dstW + (tid + 128) * 16, srcW + (size_t)(tid + 128) * 4);
        cp_async16(dstW + (tid + 256) * 16, srcW + (size_t)(tid + 256) * 4);
        cp_async16(dstW + (tid + 384) * 16, srcW + (size_t)(tid + 384) * 4);
        cp_commit();
    };

    stage(0, 0); stage(1, 1); stage(2, 2);

    constexpr int NT = Dd / 16;
    for (int t = 0; t < NT; t++) {
        if (t + 3 < NT) { stage((t + 3) & 3, t + 3); cp_wait<3>(); }
        else            { cp_wait<0>(); }
        __syncthreads();

        const float4* As4 = (const float4*)(smem + (t & 3) * STAGE_FLOATS);
        const float4* Ws4 = (const float4*)(smem + (t & 3) * STAGE_FLOATS + 1024);

        float4 bv[4];
#pragma unroll
        for (int j = 0; j < 4; j++)
            bv[j] = Ws4[(wid * 4 + j) * 32 + lane];

#pragma unroll
        for (int kk = 0; kk < 2; kk++) {
            float4 av[4];
#pragma unroll
            for (int i = 0; i < 4; i++)
                av[i] = As4[(i * 2 + kk) * 32 + lane];
#pragma unroll
            for (int i = 0; i < 4; i++)
#pragma unroll
                for (int j = 0; j < 4; j++)
                    mma_tf32(d[i][j], av[i].x, av[i].y, av[i].z, av[i].w,
                             kk ? bv[j].z : bv[j].x, kk ? bv[j].w : bv[j].y);
        }
        __syncthreads();
    }

    // Epilogue
    const int r = lane >> 2, c = lane & 3;
    const int m0 = by * 64;
    const int n0 = bx * 128 + wid * 32;
#pragma unroll
    for (int i = 0; i < 4; i++) {
#pragma unroll
        for (int j = 0; j < 4; j++) {
            int m = m0 + 16 * i + r;
            int n = n0 + 8 * j + 2 * c;
            float2 v0 = make_float2(d[i][j][0], d[i][j][1]);
            float2 v1 = make_float2(d[i][j][2], d[i][j][3]);
            if (BIAS) {
                float bx_ = bias[n], by_ = bias[n + 1];
                v0.x += bx_; v0.y += by_;
                v1.x += bx_; v1.y += by_;
            }
            *(float2*)&C[(size_t)m * Dd + n] = v0;
            *(float2*)&C[(size_t)(m + 8) * Dd + n] = v1;
        }
    }

    if (FUSE_VSUM) {
        // Column sums of this CTA's 64-row tile (V only): per-thread partials
        // over i and the two row-halves, shfl-reduce over r, atomicAdd once.
        float cs[8];
#pragma unroll
        for (int j = 0; j < 4; j++) {
            float s0 = 0.0f, s1 = 0.0f;
#pragma unroll
            for (int i = 0; i < 4; i++) {
                s0 += d[i][j][0] + d[i][j][2];
                s1 += d[i][j][1] + d[i][j][3];
            }
            cs[2 * j] = s0; cs[2 * j + 1] = s1;
        }
#pragma unroll
        for (int off = 4; off < 32; off <<= 1)
#pragma unroll
            for (int t2 = 0; t2 < 8; t2++)
                cs[t2] += __shfl_xor_sync(0xffffffffu, cs[t2], off);
        if (r == 0) {
#pragma unroll
            for (int j = 0; j < 4; j++) {
                atomicAdd(&g_vsum[n0 + 8 * j + 2 * c], cs[2 * j]);
                atomicAdd(&g_vsum[n0 + 8 * j + 2 * c + 1], cs[2 * j + 1]);
            }
        }
    }
}

__global__ __launch_bounds__(128, 4) void gemm_qkv_kernel() {
    const float* Wp = (blockIdx.z == 0) ? g_Wqp : (blockIdx.z == 1) ? g_Wkp : g_Wvp;
    float* C = (blockIdx.z == 0) ? g_Q : (blockIdx.z == 1) ? g_K : g_V;
    if (blockIdx.z == 2)
        gemm_frag_body<true, false>(g_xp, Wp, nullptr, C, blockIdx.y, blockIdx.x);
    else
        gemm_frag_body<false, false>(g_xp, Wp, nullptr, C, blockIdx.y, blockIdx.x);
}

__global__ __launch_bounds__(128, 4) void gemm_out_kernel(const float* __restrict__ bo,
                                                          float* __restrict__ out) {
    gemm_frag_body<false, true>(g_attnp, g_Wop, bo, out, blockIdx.y, blockIdx.x);
}

// ---------------------------------------------------------------------------
// Row kernel: 512 threads = 16 warps, one warp per row, block = one 16-row
// m-block. Computes att, stages in smem (pitch 260: conflict-free), then
// writes g_attnp in A-fragment-linear layout for the out-GEMM.
// ---------------------------------------------------------------------------
__device__ __forceinline__ void edge_accum(int col, int lane, const float* q,
                                           float* acc, float& dn) {
    const float* kp = g_K + (size_t)col * Dd + lane * 8;
    const float* vp = g_V + (size_t)col * Dd + lane * 8;
    float4 k1 = *(const float4*)kp;
    float4 k2 = *(const float4*)(kp + 4);
    float4 v1 = *(const float4*)vp;
    float4 v2 = *(const float4*)(vp + 4);
    float s = q[0] * k1.x + q[1] * k1.y + q[2] * k1.z + q[3] * k1.w
            + q[4] * k2.x + q[5] * k2.y + q[6] * k2.z + q[7] * k2.w;
    s += __shfl_xor_sync(0xffffffffu, s, 1);
    s += __shfl_xor_sync(0xffffffffu, s, 2);
    const float inv_scale = 0.17677669529663687f;
    float w = __expf(s * inv_scale) - 1.0f;
    acc[0] += w * v1.x; acc[1] += w * v1.y; acc[2] += w * v1.z; acc[3] += w * v1.w;
    acc[4] += w * v2.x; acc[5] += w * v2.y; acc[6] += w * v2.z; acc[7] += w * v2.w;
    dn += w;
}

__global__ __launch_bounds__(512) void row_kernel() {
    __shared__ float att_s[16 * 260];   // pitch 260 -> conflict-free chunk reads

    const int tid  = threadIdx.x;
    const int lane = tid & 31;
    const int wid  = tid >> 5;                 // 0..15: row within block
    const int row  = blockIdx.x * 16 + wid;

    const int deg = min(g_cnt[row], DCAP);
    const int* adj = g_adj + row * DCAP;

    int col0 = (lane < deg)      ? adj[lane]      : (-1 - lane);
    int col1 = (32 + lane < deg) ? adj[32 + lane] : (-1 - lane);

    unsigned m0 = __match_any_sync(0xffffffffu, col0);
    bool keep0 = (lane < deg) && (lane == __ffs(m0) - 1);
    unsigned bm0 = __ballot_sync(0xffffffffu, keep0);

    unsigned bm1 = 0u;
    if (deg > 32) {
        unsigned m1 = __match_any_sync(0xffffffffu, col1);
        bool keep1 = (32 + lane < deg) && (lane == __ffs(m1) - 1);
        for (int j = 0; j < 32; j++) {
            int cj = __shfl_sync(0xffffffffu, col0, j);
            if (j < deg && cj == col1) keep1 = false;
        }
        bm1 = __ballot_sync(0xffffffffu, keep1);
    }

    float q[8];
    {
        const float* qp = g_Q + (size_t)row * Dd + lane * 8;
        float4 a = *(const float4*)qp;
        float4 b = *(const float4*)(qp + 4);
        q[0] = a.x; q[1] = a.y; q[2] = a.z; q[3] = a.w;
        q[4] = b.x; q[5] = b.y; q[6] = b.z; q[7] = b.w;
    }

    float acc[8] = {0, 0, 0, 0, 0, 0, 0, 0};
    float dn = 0.0f;

#pragma unroll 1
    for (int ch = 0; ch < 2; ch++) {
        unsigned bm = (ch == 0) ? bm0 : bm1;
        int cols = (ch == 0) ? col0 : col1;
        while (bm) {
            int b0 = __ffs(bm) - 1; bm &= bm - 1;
            int cA = __shfl_sync(0xffffffffu, cols, b0);
            if (bm) {
                int b1 = __ffs(bm) - 1; bm &= bm - 1;
                int cB = __shfl_sync(0xffffffffu, cols, b1);
                const float* kA = g_K + (size_t)cA * Dd + lane * 8;
                const float* vA = g_V + (size_t)cA * Dd + lane * 8;
                const float* kB = g_K + (size_t)cB * Dd + lane * 8;
                const float* vB = g_V + (size_t)cB * Dd + lane * 8;
                float4 kA1 = *(const float4*)kA, kA2 = *(const float4*)(kA + 4);
                float4 vA1 = *(const float4*)vA, vA2 = *(const float4*)(vA + 4);
                float4 kB1 = *(const float4*)kB, kB2 = *(const float4*)(kB + 4);
                float4 vB1 = *(const float4*)vB, vB2 = *(const float4*)(vB + 4);

                float sA = q[0]*kA1.x + q[1]*kA1.y + q[2]*kA1.z + q[3]*kA1.w
                         + q[4]*kA2.x + q[5]*kA2.y + q[6]*kA2.z + q[7]*kA2.w;
                float sB = q[0]*kB1.x + q[1]*kB1.y + q[2]*kB1.z + q[3]*kB1.w
                         + q[4]*kB2.x + q[5]*kB2.y + q[6]*kB2.z + q[7]*kB2.w;
                sA += __shfl_xor_sync(0xffffffffu, sA, 1);
                sB += __shfl_xor_sync(0xffffffffu, sB, 1);
                sA += __shfl_xor_sync(0xffffffffu, sA, 2);
                sB += __shfl_xor_sync(0xffffffffu, sB, 2);
                const float inv_scale = 0.17677669529663687f;
                float wA = __expf(sA * inv_scale) - 1.0f;
                float wB = __expf(sB * inv_scale) - 1.0f;
                acc[0] += wA*vA1.x + wB*vB1.x; acc[1] += wA*vA1.y + wB*vB1.y;
                acc[2] += wA*vA1.z + wB*vB1.z; acc[3] += wA*vA1.w + wB*vB1.w;
                acc[4] += wA*vA2.x + wB*vB2.x; acc[5] += wA*vA2.y + wB*vB2.y;
                acc[6] += wA*vA2.z + wB*vB2.z; acc[7] += wA*vA2.w + wB*vB2.w;
                dn += wA + wB;
            } else {
                edge_accum(cA, lane, q, acc, dn);
            }
        }
    }

    // Stage att row into smem (tf32-rounded: feeds the tf32 out-GEMM)
    const float* vs = g_vsum + lane * 8;
    float inv_d = 1.0f / ((float)Nn + dn);
    float* arow = att_s + wid * 260 + lane * 8;
#pragma unroll
    for (int i = 0; i < 8; i++)
        arow[i] = tf32_rna((vs[i] + acc[i]) * inv_d);
    __syncthreads();

    // Write A-fragment-linear chunks: 1024 float4 per block, 2 per thread.
    const int mpanel = blockIdx.x >> 3;
    const int mblk   = blockIdx.x & 7;
#pragma unroll
    for (int ci = tid; ci < 1024; ci += 512) {
        int lane_c = ci & 31;
        int kk     = (ci >> 5) & 1;
        int kblk   = ci >> 6;
        int mloc   = lane_c >> 2;
        int k      = kblk * 16 + kk * 8 + (lane_c & 3);
        float4 v;
        v.x = att_s[mloc * 260 + k];
        v.y = att_s[(mloc + 8) * 260 + k];
        v.z = att_s[mloc * 260 + k + 4];
        v.w = att_s[(mloc + 8) * 260 + k + 4];
        size_t g = ((((size_t)mpanel * 16 + kblk) * 8 + mblk) * 2 + kk) * 32 + lane_c;
        ((float4*)g_attnp)[g] = v;
    }
}

// ---------------------------------------------------------------------------
extern "C" void kernel_launch(void* const* d_in, const int* in_sizes, int n_in,
                              void* d_out, int out_size) {
    const float* x  = (const float*)d_in[0];
    const int*   ei = (const int*)d_in[1];     // int32 (JAX x64 disabled)
    const float* Wq = (const float*)d_in[2];
    const float* Wk = (const float*)d_in[3];
    const float* Wv = (const float*)d_in[4];
    const float* Wo = (const float*)d_in[5];
    const float* bo = (const float*)d_in[6];
    float*       out = (float*)d_out;

    cudaFuncSetAttribute(gemm_qkv_kernel,
                         cudaFuncAttributeMaxDynamicSharedMemorySize, QKV_SMEM_BYTES);
    cudaFuncSetAttribute(gemm_out_kernel,
                         cudaFuncAttributeMaxDynamicSharedMemorySize, QKV_SMEM_BYTES);

    zero_small_kernel<<<17, 256>>>();
    bucket_kernel<<<Ee / 256, 256>>>(ei);
    permute_kernel<<<512, 256>>>(x, Wq, Wk, Wv, Wo);
    gemm_qkv_kernel<<<dim3(2, 64, 3), 128, QKV_SMEM_BYTES>>>();
    row_kernel<<<Nn / 16, 512>>>();
    gemm_out_kernel<<<dim3(2, 64, 1), 128, QKV_SMEM_BYTES>>>(bo, out);
}

// round 16
// speedup vs baseline: 1.2043x; 1.0329x over previous
#include <cuda_runtime.h>

// Problem constants
constexpr int Nn = 4096;   // nodes
constexpr int Dd = 256;    // model dim
constexpr int Ee = 65536;  // edges
constexpr int DCAP = 64;   // per-row bucket capacity

// Fragment-linear GEMM: BM=64/BN=128, 128 thr, 4 warps, warp-tile 64x32.
// 2 k-tiles per stage, 3-buffer ring, ONE barrier per stage.
constexpr int STG_FLOATS = 6144;                      // 2 x (1024 A + 2048 W)
constexpr int NSTG = 8;                               // 16 k-tiles / 2
constexpr int GEMM_SMEM_BYTES = 3 * STG_FLOATS * 4;   // 73728

// ---------------------------------------------------------------------------
// Scratch
// ---------------------------------------------------------------------------
__device__ float    g_Q[Nn * Dd];
__device__ float    g_K[Nn * Dd];
__device__ float    g_V[Nn * Dd];
__device__ float    g_attnp[Nn * Dd];   // attn in A-fragment-linear layout
__device__ float    g_vsum[Dd];
__device__ int      g_cnt[Nn];
__device__ int      g_adj[Nn * DCAP];
// permuted (fragment-linear) tf32-rounded operands
__device__ float    g_xp[Nn * Dd];
__device__ float    g_Wqp[Dd * Dd];
__device__ float    g_Wkp[Dd * Dd];
__device__ float    g_Wvp[Dd * Dd];
__device__ float    g_Wop[Dd * Dd];

// ---------------------------------------------------------------------------
__device__ __forceinline__ float tf32_rna(float f) {
    unsigned u;
    asm("cvt.rna.tf32.f32 %0, %1;" : "=r"(u) : "f"(f));
    return __uint_as_float(u);
}

__global__ void bucket_kernel(const int* __restrict__ ei) {
    int e = blockIdx.x * blockDim.x + threadIdx.x;
    if (e >= Ee) return;
    int row = ei[e] & (Nn - 1);
    int col = ei[Ee + e] & (Nn - 1);
    int p = atomicAdd(&g_cnt[row], 1);
    if (p < DCAP) g_adj[row * DCAP + p] = col;
}

// ---------------------------------------------------------------------------
// Permute + tf32-round pass; also zeroes g_cnt / g_vsum (fused launch).
// ---------------------------------------------------------------------------
__global__ void permute_kernel(const float* __restrict__ x,
                               const float* __restrict__ Wq,
                               const float* __restrict__ Wk,
                               const float* __restrict__ Wv,
                               const float* __restrict__ Wo) {
    int idx = blockIdx.x * blockDim.x + threadIdx.x;
    int stride = gridDim.x * blockDim.x;

    if (idx < Nn) g_cnt[idx] = 0;
    if (idx < Dd) g_vsum[idx] = 0.0f;

    for (int cidx = idx; cidx < Nn * Dd / 4; cidx += stride) {
        int lane   = cidx & 31;
        int kk     = (cidx >> 5) & 1;
        int mblk   = (cidx >> 6) & 7;
        int kblk   = (cidx >> 9) & 15;
        int mpanel = cidx >> 13;
        int m = mpanel * 128 + mblk * 16 + (lane >> 2);
        int k = kblk * 16 + kk * 8 + (lane & 3);
        float4 v;
        v.x = tf32_rna(x[(size_t)m * Dd + k]);
        v.y = tf32_rna(x[(size_t)(m + 8) * Dd + k]);
        v.z = tf32_rna(x[(size_t)m * Dd + k + 4]);
        v.w = tf32_rna(x[(size_t)(m + 8) * Dd + k + 4]);
        ((float4*)g_xp)[cidx] = v;
    }

    for (int cidx = idx; cidx < Dd * Dd / 4; cidx += stride) {
        int lane   = cidx & 31;
        int nblk   = (cidx >> 5) & 15;
        int kblk   = (cidx >> 9) & 15;
        int npanel = cidx >> 13;
        int n  = npanel * 128 + nblk * 8 + (lane >> 2);
        int kb = kblk * 16 + (lane & 3);
        size_t s = (size_t)n * Dd + kb;
        float4 vq, vk, vv, vo;
        vq.x = tf32_rna(Wq[s]);      vq.y = tf32_rna(Wq[s + 4]);
        vq.z = tf32_rna(Wq[s + 8]);  vq.w = tf32_rna(Wq[s + 12]);
        vk.x = tf32_rna(Wk[s]);      vk.y = tf32_rna(Wk[s + 4]);
        vk.z = tf32_rna(Wk[s + 8]);  vk.w = tf32_rna(Wk[s + 12]);
        vv.x = tf32_rna(Wv[s]);      vv.y = tf32_rna(Wv[s + 4]);
        vv.z = tf32_rna(Wv[s + 8]);  vv.w = tf32_rna(Wv[s + 12]);
        vo.x = tf32_rna(Wo[s]);      vo.y = tf32_rna(Wo[s + 4]);
        vo.z = tf32_rna(Wo[s + 8]);  vo.w = tf32_rna(Wo[s + 12]);
        ((float4*)g_Wqp)[cidx] = vq;
        ((float4*)g_Wkp)[cidx] = vk;
        ((float4*)g_Wvp)[cidx] = vv;
        ((float4*)g_Wop)[cidx] = vo;
    }
}

// ---------------------------------------------------------------------------
// Shared GEMM helpers
// ---------------------------------------------------------------------------
__device__ __forceinline__ unsigned smem_u32(const void* p) {
    return (unsigned)__cvta_generic_to_shared(p);
}
__device__ __forceinline__ void cp_async16(unsigned dst, const void* src) {
    asm volatile("cp.async.cg.shared.global [%0], [%1], 16;" :: "r"(dst), "l"(src));
}
__device__ __forceinline__ void cp_commit() {
    asm volatile("cp.async.commit_group;" ::: "memory");
}
template <int N> __device__ __forceinline__ void cp_wait() {
    asm volatile("cp.async.wait_group %0;" :: "n"(N) : "memory");
}
__device__ __forceinline__ void mma_tf32(float* d, float a0, float a1, float a2, float a3,
                                         float b0, float b1) {
    asm volatile(
        "mma.sync.aligned.m16n8k8.row.col.f32.tf32.tf32.f32 "
        "{%0,%1,%2,%3}, {%4,%5,%6,%7}, {%8,%9}, {%0,%1,%2,%3};\n"
        : "+f"(d[0]), "+f"(d[1]), "+f"(d[2]), "+f"(d[3])
        : "r"(__float_as_uint(a0)), "r"(__float_as_uint(a1)),
          "r"(__float_as_uint(a2)), "r"(__float_as_uint(a3)),
          "r"(__float_as_uint(b0)), "r"(__float_as_uint(b1)));
}

// ---------------------------------------------------------------------------
// Fragment-linear GEMM body: 2 k-tiles per stage, 3-buffer ring, 1 barrier
// per stage (8 total). Ring safety: prefetch(st+2) at iter st (post-barrier)
// overwrites buffer (st-1)%3, whose readers all passed this barrier; cp.async
// groups complete in order so wait_group(1) is exact for stage st.
// ---------------------------------------------------------------------------
template <bool FUSE_VSUM, bool BIAS>
__device__ __forceinline__ void gemm_frag_body(const float* __restrict__ Ap,
                                               const float* __restrict__ Wp,
                                               const float* __restrict__ bias,
                                               float* __restrict__ C,
                                               int by, int bx) {
    extern __shared__ __align__(16) float smem[];
    const int tid  = threadIdx.x;
    const int lane = tid & 31;
    const int wid  = tid >> 5;          // 0..3 -> n-block group
    const unsigned sbase = smem_u32(smem);

    const int mp128 = by >> 1;
    const int half  = by & 1;

    float d[4][4][4];
#pragma unroll
    for (int i = 0; i < 4; i++)
#pragma unroll
        for (int j = 0; j < 4; j++)
#pragma unroll
            for (int q = 0; q < 4; q++) d[i][j][q] = 0.0f;

    auto stage = [&](int st) {
        unsigned base = sbase + (unsigned)((st % 3) * STG_FLOATS) * 4u;
#pragma unroll
        for (int kt = 0; kt < 2; kt++) {
            int t = 2 * st + kt;
            unsigned dstA = base + kt * 3072 * 4;
            const float* srcA = Ap + ((size_t)mp128 * 16 + t) * 2048 + half * 1024;
            cp_async16(dstA + tid * 16, srcA + (size_t)tid * 4);
            cp_async16(dstA + (tid + 128) * 16, srcA + (size_t)(tid + 128) * 4);
            unsigned dstW = dstA + 1024 * 4;
            const float* srcW = Wp + ((size_t)bx * 16 + t) * 2048;
            cp_async16(dstW + tid * 16, srcW + (size_t)tid * 4);
            cp_async16(dstW + (tid + 128) * 16, srcW + (size_t)(tid + 128) * 4);
            cp_async16(dstW + (tid + 256) * 16, srcW + (size_t)(tid + 256) * 4);
            cp_async16(dstW + (tid + 384) * 16, srcW + (size_t)(tid + 384) * 4);
        }
        cp_commit();
    };

    stage(0); stage(1); stage(2);

    for (int st = 0; st < NSTG; st++) {
        if (st < NSTG - 1) cp_wait<1>();
        else               cp_wait<0>();
        __syncthreads();
        if (st >= 1 && st + 2 < NSTG) stage(st + 2);

#pragma unroll
        for (int kt = 0; kt < 2; kt++) {
            const float4* As4 = (const float4*)(smem + (st % 3) * STG_FLOATS + kt * 3072);
            const float4* Ws4 = (const float4*)(smem + (st % 3) * STG_FLOATS + kt * 3072 + 1024);

            float4 bv[4];
#pragma unroll
            for (int j = 0; j < 4; j++)
                bv[j] = Ws4[(wid * 4 + j) * 32 + lane];

#pragma unroll
            for (int kk = 0; kk < 2; kk++) {
                float4 av[4];
#pragma unroll
                for (int i = 0; i < 4; i++)
                    av[i] = As4[(i * 2 + kk) * 32 + lane];
#pragma unroll
                for (int i = 0; i < 4; i++)
#pragma unroll
                    for (int j = 0; j < 4; j++)
                        mma_tf32(d[i][j], av[i].x, av[i].y, av[i].z, av[i].w,
                                 kk ? bv[j].z : bv[j].x, kk ? bv[j].w : bv[j].y);
            }
        }
    }

    // Epilogue
    const int r = lane >> 2, c = lane & 3;
    const int m0 = by * 64;
    const int n0 = bx * 128 + wid * 32;
#pragma unroll
    for (int i = 0; i < 4; i++) {
#pragma unroll
        for (int j = 0; j < 4; j++) {
            int m = m0 + 16 * i + r;
            int n = n0 + 8 * j + 2 * c;
            float2 v0 = make_float2(d[i][j][0], d[i][j][1]);
            float2 v1 = make_float2(d[i][j][2], d[i][j][3]);
            if (BIAS) {
                float bx_ = bias[n], by_ = bias[n + 1];
                v0.x += bx_; v0.y += by_;
                v1.x += bx_; v1.y += by_;
            }
            *(float2*)&C[(size_t)m * Dd + n] = v0;
            *(float2*)&C[(size_t)(m + 8) * Dd + n] = v1;
        }
    }

    if (FUSE_VSUM) {
        float cs[8];
#pragma unroll
        for (int j = 0; j < 4; j++) {
            float s0 = 0.0f, s1 = 0.0f;
#pragma unroll
            for (int i = 0; i < 4; i++) {
                s0 += d[i][j][0] + d[i][j][2];
                s1 += d[i][j][1] + d[i][j][3];
            }
            cs[2 * j] = s0; cs[2 * j + 1] = s1;
        }
#pragma unroll
        for (int off = 4; off < 32; off <<= 1)
#pragma unroll
            for (int t2 = 0; t2 < 8; t2++)
                cs[t2] += __shfl_xor_sync(0xffffffffu, cs[t2], off);
        if (r == 0) {
#pragma unroll
            for (int j = 0; j < 4; j++) {
                atomicAdd(&g_vsum[n0 + 8 * j + 2 * c], cs[2 * j]);
                atomicAdd(&g_vsum[n0 + 8 * j + 2 * c + 1], cs[2 * j + 1]);
            }
        }
    }
}

__global__ __launch_bounds__(128, 3) void gemm_qkv_kernel() {
    const float* Wp = (blockIdx.z == 0) ? g_Wqp : (blockIdx.z == 1) ? g_Wkp : g_Wvp;
    float* C = (blockIdx.z == 0) ? g_Q : (blockIdx.z == 1) ? g_K : g_V;
    if (blockIdx.z == 2)
        gemm_frag_body<true, false>(g_xp, Wp, nullptr, C, blockIdx.y, blockIdx.x);
    else
        gemm_frag_body<false, false>(g_xp, Wp, nullptr, C, blockIdx.y, blockIdx.x);
}

__global__ __launch_bounds__(128, 3) void gemm_out_kernel(const float* __restrict__ bo,
                                                          float* __restrict__ out) {
    gemm_frag_body<false, true>(g_attnp, g_Wop, bo, out, blockIdx.y, blockIdx.x);
}

// ---------------------------------------------------------------------------
// Row kernel: 512 threads = 16 warps, one warp per row; writes g_attnp in
// A-fragment-linear layout via a conflict-free smem staging tile.
// ---------------------------------------------------------------------------
__device__ __forceinline__ void edge_accum(int col, int lane, const float* q,
                                           float* acc, float& dn) {
    const float* kp = g_K + (size_t)col * Dd + lane * 8;
    const float* vp = g_V + (size_t)col * Dd + lane * 8;
    float4 k1 = *(const float4*)kp;
    float4 k2 = *(const float4*)(kp + 4);
    float4 v1 = *(const float4*)vp;
    float4 v2 = *(const float4*)(vp + 4);
    float s = q[0] * k1.x + q[1] * k1.y + q[2] * k1.z + q[3] * k1.w
            + q[4] * k2.x + q[5] * k2.y + q[6] * k2.z + q[7] * k2.w;
    s += __shfl_xor_sync(0xffffffffu, s, 1);
    s += __shfl_xor_sync(0xffffffffu, s, 2);
    const float inv_scale = 0.17677669529663687f;
    float w = __expf(s * inv_scale) - 1.0f;
    acc[0] += w * v1.x; acc[1] += w * v1.y; acc[2] += w * v1.z; acc[3] += w * v1.w;
    acc[4] += w * v2.x; acc[5] += w * v2.y; acc[6] += w * v2.z; acc[7] += w * v2.w;
    dn += w;
}

__global__ __launch_bounds__(512) void row_kernel() {
    __shared__ float att_s[16 * 260];   // pitch 260 -> conflict-free chunk reads

    const int tid  = threadIdx.x;
    const int lane = tid & 31;
    const int wid  = tid >> 5;                 // 0..15: row within block
    const int row  = blockIdx.x * 16 + wid;

    const int deg = min(g_cnt[row], DCAP);
    const int* adj = g_adj + row * DCAP;

    int col0 = (lane < deg)      ? adj[lane]      : (-1 - lane);
    int col1 = (32 + lane < deg) ? adj[32 + lane] : (-1 - lane);

    unsigned m0 = __match_any_sync(0xffffffffu, col0);
    bool keep0 = (lane < deg) && (lane == __ffs(m0) - 1);
    unsigned bm0 = __ballot_sync(0xffffffffu, keep0);

    unsigned bm1 = 0u;
    if (deg > 32) {
        unsigned m1 = __match_any_sync(0xffffffffu, col1);
        bool keep1 = (32 + lane < deg) && (lane == __ffs(m1) - 1);
        for (int j = 0; j < 32; j++) {
            int cj = __shfl_sync(0xffffffffu, col0, j);
            if (j < deg && cj == col1) keep1 = false;
        }
        bm1 = __ballot_sync(0xffffffffu, keep1);
    }

    float q[8];
    {
        const float* qp = g_Q + (size_t)row * Dd + lane * 8;
        float4 a = *(const float4*)qp;
        float4 b = *(const float4*)(qp + 4);
        q[0] = a.x; q[1] = a.y; q[2] = a.z; q[3] = a.w;
        q[4] = b.x; q[5] = b.y; q[6] = b.z; q[7] = b.w;
    }

    float acc[8] = {0, 0, 0, 0, 0, 0, 0, 0};
    float dn = 0.0f;

#pragma unroll 1
    for (int ch = 0; ch < 2; ch++) {
        unsigned bm = (ch == 0) ? bm0 : bm1;
        int cols = (ch == 0) ? col0 : col1;
        while (bm) {
            int b0 = __ffs(bm) - 1; bm &= bm - 1;
            int cA = __shfl_sync(0xffffffffu, cols, b0);
            if (bm) {
                int b1 = __ffs(bm) - 1; bm &= bm - 1;
                int cB = __shfl_sync(0xffffffffu, cols, b1);
                const float* kA = g_K + (size_t)cA * Dd + lane * 8;
                const float* vA = g_V + (size_t)cA * Dd + lane * 8;
                const float* kB = g_K + (size_t)cB * Dd + lane * 8;
                const float* vB = g_V + (size_t)cB * Dd + lane * 8;
                float4 kA1 = *(const float4*)kA, kA2 = *(const float4*)(kA + 4);
                float4 vA1 = *(const float4*)vA, vA2 = *(const float4*)(vA + 4);
                float4 kB1 = *(const float4*)kB, kB2 = *(const float4*)(kB + 4);
                float4 vB1 = *(const float4*)vB, vB2 = *(const float4*)(vB + 4);

                float sA = q[0]*kA1.x + q[1]*kA1.y + q[2]*kA1.z + q[3]*kA1.w
                         + q[4]*kA2.x + q[5]*kA2.y + q[6]*kA2.z + q[7]*kA2.w;
                float sB = q[0]*kB1.x + q[1]*kB1.y + q[2]*kB1.z + q[3]*kB1.w
                         + q[4]*kB2.x + q[5]*kB2.y + q[6]*kB2.z + q[7]*kB2.w;
                sA += __shfl_xor_sync(0xffffffffu, sA, 1);
                sB += __shfl_xor_sync(0xffffffffu, sB, 1);
                sA += __shfl_xor_sync(0xffffffffu, sA, 2);
                sB += __shfl_xor_sync(0xffffffffu, sB, 2);
                const float inv_scale = 0.17677669529663687f;
                float wA = __expf(sA * inv_scale) - 1.0f;
                float wB = __expf(sB * inv_scale) - 1.0f;
                acc[0] += wA*vA1.x + wB*vB1.x; acc[1] += wA*vA1.y + wB*vB1.y;
                acc[2] += wA*vA1.z + wB*vB1.z; acc[3] += wA*vA1.w + wB*vB1.w;
                acc[4] += wA*vA2.x + wB*vB2.x; acc[5] += wA*vA2.y + wB*vB2.y;
                acc[6] += wA*vA2.z + wB*vB2.z; acc[7] += wA*vA2.w + wB*vB2.w;
                dn += wA + wB;
            } else {
                edge_accum(cA, lane, q, acc, dn);
            }
        }
    }

    // Stage att row into smem (tf32-rounded: feeds the tf32 out-GEMM)
    const float* vs = g_vsum + lane * 8;
    float inv_d = 1.0f / ((float)Nn + dn);
    float* arow = att_s + wid * 260 + lane * 8;
#pragma unroll
    for (int i = 0; i < 8; i++)
        arow[i] = tf32_rna((vs[i] + acc[i]) * inv_d);
    __syncthreads();

    // Write A-fragment-linear chunks: 1024 float4 per block, 2 per thread.
    const int mpanel = blockIdx.x >> 3;
    const int mblk   = blockIdx.x & 7;
#pragma unroll
    for (int ci = tid; ci < 1024; ci += 512) {
        int lane_c = ci & 31;
        int kk     = (ci >> 5) & 1;
        int kblk   = ci >> 6;
        int mloc   = lane_c >> 2;
        int k      = kblk * 16 + kk * 8 + (lane_c & 3);
        float4 v;
        v.x = att_s[mloc * 260 + k];
        v.y = att_s[(mloc + 8) * 260 + k];
        v.z = att_s[mloc * 260 + k + 4];
        v.w = att_s[(mloc + 8) * 260 + k + 4];
        size_t g = ((((size_t)mpanel * 16 + kblk) * 8 + mblk) * 2 + kk) * 32 + lane_c;
        ((float4*)g_attnp)[g] = v;
    }
}

// ---------------------------------------------------------------------------
extern "C" void kernel_launch(void* const* d_in, const int* in_sizes, int n_in,
                              void* d_out, int out_size) {
    const float* x  = (const float*)d_in[0];
    const int*   ei = (const int*)d_in[1];     // int32 (JAX x64 disabled)
    const float* Wq = (const float*)d_in[2];
    const float* Wk = (const float*)d_in[3];
    const float* Wv = (const float*)d_in[4];
    const float* Wo = (const float*)d_in[5];
    const float* bo = (const float*)d_in[6];
    float*       out = (float*)d_out;

    cudaFuncSetAttribute(gemm_qkv_kernel,
                         cudaFuncAttributeMaxDynamicSharedMemorySize, GEMM_SMEM_BYTES);
    cudaFuncSetAttribute(gemm_out_kernel,
                         cudaFuncAttributeMaxDynamicSharedMemorySize, GEMM_SMEM_BYTES);

    permute_kernel<<<512, 256>>>(x, Wq, Wk, Wv, Wo);   // also zeroes cnt/vsum
    bucket_kernel<<<Ee / 256, 256>>>(ei);
    gemm_qkv_kernel<<<dim3(2, 64, 3), 128, GEMM_SMEM_BYTES>>>();
    row_kernel<<<Nn / 16, 512>>>();
    gemm_out_kernel<<<dim3(2, 64, 1), 128, GEMM_SMEM_BYTES>>>(bo, out);
}